// round 2
// baseline (speedup 1.0000x reference)
#include <cuda_runtime.h>

// Problem constants (from reference setup_inputs)
#define B_   4
#define IC   16      // inDim
#define S_   4096    // nSeq
#define O_   64      // outDim
#define W_   64      // nWin
#define OH   32      // outputs per CTA (O split in 2)
#define TT   256     // time-tile per CTA
#define ECH  8       // events per chunk

// Shared memory layout (floats)
#define WSM_FLOATS (IC*16*OH*4)        // 32768 : weight, layout [i][wq][o][4]
#define TRF_FLOATS (ECH*OH*65)         // 16640 : trf[e][o][w], row stride 65 (conflict-free)
#define TRF_OFF    (WSM_FLOATS)
#define XS2_OFF    (TRF_OFF + TRF_FLOATS)   // x duplicated pairs [i][e2][4]
#define XS2_FLOATS (IC*4*4)            // 256
#define SRC_OFF    (XS2_OFF + XS2_FLOATS)
#define SMEM_FLOATS (SRC_OFF + 16)
#define SMEM_BYTES  (SMEM_FLOATS * 4)  // 198720 B < 227 KB

__device__ __forceinline__ unsigned long long ffma2(unsigned long long a,
                                                    unsigned long long b,
                                                    unsigned long long c) {
    unsigned long long d;
    asm("fma.rn.f32x2 %0, %1, %2, %3;" : "=l"(d) : "l"(a), "l"(b), "l"(c));
    return d;
}
__device__ __forceinline__ unsigned long long pack2(float lo, float hi) {
    unsigned long long d;
    asm("mov.b64 %0, {%1, %2};" : "=l"(d) : "f"(lo), "f"(hi));
    return d;
}
__device__ __forceinline__ void unpack2(unsigned long long v, float& lo, float& hi) {
    asm("mov.b64 {%0, %1}, %2;" : "=f"(lo), "=f"(hi) : "l"(v));
}

__global__ __launch_bounds__(512, 1)
void astrf_kernel(const float* __restrict__ x, const float* __restrict__ wt,
                  const float* __restrict__ bias, const int* __restrict__ srcIdx,
                  float* __restrict__ out, int T)
{
    extern __shared__ float smem[];
    float* wsm   = smem;
    float* trf   = smem + TRF_OFF;
    float* xs2   = smem + XS2_OFF;
    int*   srcsm = (int*)(smem + SRC_OFF);
    int*   ctrl  = (int*)(smem + SRC_OFF + ECH);

    const int tid   = threadIdx.x;
    const int b     = blockIdx.z;
    const int oBase = blockIdx.y * OH;
    const int t0    = blockIdx.x * TT;

    // ---- Stage weight slice into smem, transposed to [i][wq][o][k] so that
    // Phase-A LDS.128 with lanes over o is conflict-free.
    {
        const int o = tid & 31;
        const int q = tid >> 5;
        const float4* gw = (const float4*)(wt + (size_t)(oBase + o) * (IC * W_));
        float4* wsm4 = (float4*)wsm;
        #pragma unroll
        for (int u = 0; u < 8; u++) {
            int unit = q + u * 16;          // 0..127 : (i, wq-pair)
            int i = unit >> 3, wp = unit & 7;
            float4 a  = gw[i * 16 + wp * 2];       // 32B contiguous per lane
            float4 bb = gw[i * 16 + wp * 2 + 1];
            wsm4[(i * 16 + 2 * wp)     * 32 + o] = a;
            wsm4[(i * 16 + 2 * wp + 1) * 32 + o] = bb;
        }
    }

    // ---- Binary search event window: src in [t0-(W-1), t0+TT)
    if (tid == 0) {
        const int* sp = srcIdx + b * S_;
        int lo = 0, hi = S_, tgt = t0 - (W_ - 1);
        while (lo < hi) { int m = (lo + hi) >> 1; if (sp[m] < tgt) lo = m + 1; else hi = m; }
        ctrl[0] = lo;
        lo = 0; hi = S_; tgt = t0 + TT;
        while (lo < hi) { int m = (lo + hi) >> 1; if (sp[m] < tgt) lo = m + 1; else hi = m; }
        ctrl[1] = lo;
    }
    __syncthreads();
    const int sLo = ctrl[0], sHi = ctrl[1];

    // Phase-A thread ids
    const int oA = tid & 31, wqA = tid >> 5;           // o lane, w-quad
    // Phase-B thread ids
    const int lane = tid & 31, wid = tid >> 5;
    const int ohB = wid >> 3;                          // which 16-o slab
    const int tsB = (wid & 7) * 32;                    // 32-t slab, lanes = consecutive t

    float acc[16];
    #pragma unroll
    for (int o = 0; o < 16; o++) acc[o] = 0.f;

    for (int c0 = sLo; c0 < sHi; c0 += ECH) {
        const int nE = min(ECH, sHi - c0);

        // ---- Stage x (duplicated into f32x2 pairs) and src values
        if (tid < 128) {
            int e = tid >> 4, i = tid & 15;
            float v = (e < nE) ? x[(size_t)(b * IC + i) * S_ + c0 + e] : 0.f;
            int idx = (i * 4 + (e >> 1)) * 4 + (e & 1) * 2;
            xs2[idx] = v; xs2[idx + 1] = v;
        }
        if (tid < ECH) srcsm[tid] = (tid < nE) ? srcIdx[b * S_ + c0 + tid] : -0x40000000;
        __syncthreads();

        // ---- Phase A: trf[e][o][wq*4..+3] = sum_i x[i,e] * w[o,i,w]
        unsigned long long a2[ECH][2];
        #pragma unroll
        for (int e = 0; e < ECH; e++) { a2[e][0] = 0ull; a2[e][1] = 0ull; }

        const float4* wA = (const float4*)wsm + (wqA * 32 + oA);
        const ulonglong2* xA = (const ulonglong2*)xs2;
        #pragma unroll
        for (int i = 0; i < IC; i++) {
            float4 wv = wA[i * 512];                   // conflict-free LDS.128
            unsigned long long w01 = pack2(wv.x, wv.y);
            unsigned long long w23 = pack2(wv.z, wv.w);
            #pragma unroll
            for (int e2 = 0; e2 < 4; e2++) {
                ulonglong2 xv = xA[i * 4 + e2];        // broadcast LDS.128: 2 dup-pairs
                a2[2*e2  ][0] = ffma2(w01, xv.x, a2[2*e2  ][0]);
                a2[2*e2  ][1] = ffma2(w23, xv.x, a2[2*e2  ][1]);
                a2[2*e2+1][0] = ffma2(w01, xv.y, a2[2*e2+1][0]);
                a2[2*e2+1][1] = ffma2(w23, xv.y, a2[2*e2+1][1]);
            }
        }
        // store trf (stride-65 rows -> conflict-free STS.32 over o-lanes)
        #pragma unroll
        for (int e = 0; e < ECH; e++) {
            float f0, f1, f2, f3;
            unpack2(a2[e][0], f0, f1);
            unpack2(a2[e][1], f2, f3);
            float* p = trf + (e * 32 + oA) * 65 + wqA * 4;
            p[0] = f0; p[1] = f1; p[2] = f2; p[3] = f3;
        }
        __syncthreads();

        // ---- Phase B: overlap-add into register accumulators (no atomics)
        const float* tb = trf + (ohB * 16) * 65;
        for (int e = 0; e < nE; e++) {
            int wbase = tsB - (srcsm[e] - t0);         // warp-uniform
            if (wbase > 63 || wbase < -31) continue;
            int w = wbase + lane;
            if (w >= 0 && w < W_) {
                const float* tp = tb + e * (32 * 65) + w;
                #pragma unroll
                for (int o = 0; o < 16; o++) acc[o] += tp[o * 65];
            }
        }
        __syncthreads();
    }

    // ---- Epilogue: bias + coalesced store (lanes = consecutive t)
    const int t = t0 + tsB + lane;
    if (t < T) {
        #pragma unroll
        for (int o = 0; o < 16; o++) {
            int og = oBase + ohB * 16 + o;
            out[(size_t)(b * O_ + og) * T + t] = acc[o] + __ldg(bias + og);
        }
    }
}

extern "C" void kernel_launch(void* const* d_in, const int* in_sizes, int n_in,
                              void* d_out, int out_size) {
    (void)in_sizes; (void)n_in;
    const float* x    = (const float*)d_in[0];
    const float* wt   = (const float*)d_in[1];
    const float* bias = (const float*)d_in[2];
    const int*   src  = (const int*)d_in[3];
    float* out = (float*)d_out;

    int T = out_size / (B_ * O_);   // 32768
    cudaFuncSetAttribute(astrf_kernel, cudaFuncAttributeMaxDynamicSharedMemorySize, SMEM_BYTES);
    dim3 grid((T + TT - 1) / TT, O_ / OH, B_);
    astrf_kernel<<<grid, 512, SMEM_BYTES>>>(x, wt, bias, src, out, T);
}

// round 3
// speedup vs baseline: 1.1975x; 1.1975x over previous
#include <cuda_runtime.h>

// Problem constants
#define B_   4
#define IC   16      // inDim
#define S_   4096    // nSeq
#define O_   64      // outDim
#define W_   64      // nWin
#define OH   16      // outputs per CTA
#define TT   256     // time-tile per CTA
#define ECH  8       // events per chunk

// Shared memory layout (float offsets)
//  wsm : [i*16+wq][o^ (row&15)][4]  -> 256 rows x 16 float4 = 16384 floats (64KB)
//  trf : [e*64+w][20] (o padded 16->20) -> 512*20 = 10240 floats (40KB)
//  xs2 : 2 buffers x [i*16 + e*2] dup pairs = 2*256 floats
//  src : 2 buffers x 8 ints
#define WSM_FLOATS 16384
#define TRF_OFF    16384
#define TRF_FLOATS 10240
#define XS2_OFF    (TRF_OFF + TRF_FLOATS)       // 26624
#define SRC_OFF    (XS2_OFF + 512)              // 27136
#define SMEM_FLOATS (SRC_OFF + 24)
#define SMEM_BYTES  (SMEM_FLOATS * 4)           // ~108.6 KB

__device__ __forceinline__ unsigned long long ffma2(unsigned long long a,
                                                    unsigned long long b,
                                                    unsigned long long c) {
    unsigned long long d;
    asm("fma.rn.f32x2 %0, %1, %2, %3;" : "=l"(d) : "l"(a), "l"(b), "l"(c));
    return d;
}
__device__ __forceinline__ unsigned long long add2(unsigned long long a,
                                                   unsigned long long b) {
    unsigned long long d;
    asm("add.rn.f32x2 %0, %1, %2;" : "=l"(d) : "l"(a), "l"(b));
    return d;
}
__device__ __forceinline__ unsigned long long pack2(float lo, float hi) {
    unsigned long long d;
    asm("mov.b64 %0, {%1, %2};" : "=l"(d) : "f"(lo), "f"(hi));
    return d;
}
__device__ __forceinline__ void unpack2(unsigned long long v, float& lo, float& hi) {
    asm("mov.b64 {%0, %1}, %2;" : "=f"(lo), "=f"(hi) : "l"(v));
}

__global__ __launch_bounds__(512, 2)
void astrf_kernel(const float* __restrict__ x, const float* __restrict__ wt,
                  const float* __restrict__ bias, const int* __restrict__ srcIdx,
                  float* __restrict__ out, int T)
{
    extern __shared__ float smem[];
    float* wsm   = smem;
    float* trf   = smem + TRF_OFF;
    float* xs2   = smem + XS2_OFF;
    int*   srcsm = (int*)(smem + SRC_OFF);

    const int tid   = threadIdx.x;
    const int b     = blockIdx.z;
    const int oBase = blockIdx.y * OH;
    const int t0    = blockIdx.x * TT;

    // ---- Stage weight slice: coalesced gmem loads, XOR-swizzled smem stores.
    {
        const int o    = tid >> 5;          // warp id = output channel
        const int lane = tid & 31;
        const float4* gw = (const float4*)(wt + (size_t)(oBase + o) * (IC * W_));
        float4* wsm4 = (float4*)wsm;
        #pragma unroll
        for (int u = 0; u < 8; u++) {
            int row = lane + u * 32;                    // 0..255 = i*16 + wq
            wsm4[row * 16 + (o ^ (row & 15))] = gw[row]; // conflict-free swizzle store
        }
    }

    // ---- Per-thread binary search for event window [t0-(W-1), t0+TT)
    int sLo, sHi;
    {
        const int* sp = srcIdx + b * S_;
        int lo = 0, hi = S_, tgt = t0 - (W_ - 1);
        while (lo < hi) { int m = (lo + hi) >> 1; if (sp[m] < tgt) lo = m + 1; else hi = m; }
        sLo = lo;
        lo = 0; hi = S_; tgt = t0 + TT;
        while (lo < hi) { int m = (lo + hi) >> 1; if (sp[m] < tgt) lo = m + 1; else hi = m; }
        sHi = lo;
    }

    // Thread roles
    const int oA  = tid & 15;            // Phase A: output lane
    const int wqA = (tid >> 4) & 15;     // Phase A: w-quad
    const int egA = tid >> 8;            // Phase A/B: event group (0/1)
    const int tlB = tid & 255;           // Phase B: time offset within tile

    // Phase-A weight pointer (swizzle term == wqA, constant per thread)
    const float4* wA = (const float4*)wsm + wqA * 16 + (oA ^ wqA);

    // Persistent accumulators: 16 outputs as 8 f32x2
    unsigned long long acc2[8];
    #pragma unroll
    for (int k = 0; k < 8; k++) acc2[k] = 0ull;

    // ---- Stage chunk 0 (x dup-pairs + src)
    auto stage = [&](int c0, int buf) {
        if (tid < 128) {
            int i = tid >> 3, e = tid & 7;
            float v = (c0 + e < sHi) ? x[(size_t)(b * IC + i) * S_ + c0 + e] : 0.f;
            float* p = xs2 + buf * 256 + i * 16 + e * 2;
            p[0] = v; p[1] = v;
        } else if (tid < 136) {
            int k = tid - 128;
            srcsm[buf * 8 + k] = (c0 + k < sHi) ? srcIdx[b * S_ + c0 + k] : (1 << 29);
        }
    };
    stage(sLo, 0);
    __syncthreads();

    int cur = 0;
    for (int c0 = sLo; c0 < sHi; c0 += ECH) {
        // ---- Phase A: trf[e][w][o] = sum_i x[i,e] * w[o,i,w]
        unsigned long long a2[4][2];
        #pragma unroll
        for (int le = 0; le < 4; le++) { a2[le][0] = 0ull; a2[le][1] = 0ull; }

        const float* xb = xs2 + cur * 256 + egA * 8;
        #pragma unroll
        for (int i = 0; i < IC; i++) {
            float4 wv = wA[i * 256];                       // conflict-free LDS.128
            unsigned long long w01 = pack2(wv.x, wv.y);
            unsigned long long w23 = pack2(wv.z, wv.w);
            const ulonglong2* xp = (const ulonglong2*)(xb + i * 16);
            #pragma unroll
            for (int ep = 0; ep < 2; ep++) {
                ulonglong2 xv = xp[ep];                    // broadcast LDS.128
                a2[2*ep  ][0] = ffma2(w01, xv.x, a2[2*ep  ][0]);
                a2[2*ep  ][1] = ffma2(w23, xv.x, a2[2*ep  ][1]);
                a2[2*ep+1][0] = ffma2(w01, xv.y, a2[2*ep+1][0]);
                a2[2*ep+1][1] = ffma2(w23, xv.y, a2[2*ep+1][1]);
            }
        }
        // store trf rows (e*64 + wq*4 + k), offset o : conflict-free halves
        #pragma unroll
        for (int le = 0; le < 4; le++) {
            int e = egA * 4 + le;
            float f0, f1, f2, f3;
            unpack2(a2[le][0], f0, f1);
            unpack2(a2[le][1], f2, f3);
            float* p = trf + (e * 64 + wqA * 4) * 20 + oA;
            p[0] = f0; p[20] = f1; p[40] = f2; p[60] = f3;
        }
        __syncthreads();   // trf ready; xs2[cur] fully consumed

        // ---- Stage next chunk into the other buffer (overlaps Phase B)
        if (c0 + ECH < sHi) stage(c0 + ECH, cur ^ 1);

        // ---- Phase B: overlap-add, 4 LDS.128 per event, no atomics
        {
            const int t = t0 + tlB;
            const int* sp = srcsm + cur * 8 + egA * 4;
            #pragma unroll
            for (int le = 0; le < 4; le++) {
                int w = t - sp[le];
                if ((unsigned)w < (unsigned)W_) {
                    int e = egA * 4 + le;
                    const ulonglong2* p =
                        (const ulonglong2*)(trf + (e * 64 + w) * 20);
                    #pragma unroll
                    for (int j = 0; j < 4; j++) {
                        ulonglong2 v = p[j];
                        acc2[2*j]   = add2(acc2[2*j],   v.x);
                        acc2[2*j+1] = add2(acc2[2*j+1], v.y);
                    }
                }
            }
        }
        __syncthreads();   // Phase B done reading trf; next x staged
        cur ^= 1;
    }

    // ---- Epilogue: combine the two event-group partials, add bias, store
    if (egA == 1) {
        ulonglong2* bp = (ulonglong2*)trf + tlB * 4;
        #pragma unroll
        for (int j = 0; j < 4; j++) {
            ulonglong2 v; v.x = acc2[2*j]; v.y = acc2[2*j+1];
            bp[j] = v;
        }
    }
    __syncthreads();
    if (egA == 0) {
        const ulonglong2* bp = (const ulonglong2*)trf + tlB * 4;
        #pragma unroll
        for (int j = 0; j < 4; j++) {
            ulonglong2 v = bp[j];
            acc2[2*j]   = add2(acc2[2*j],   v.x);
            acc2[2*j+1] = add2(acc2[2*j+1], v.y);
        }
        const int t = t0 + tlB;
        #pragma unroll
        for (int j = 0; j < 8; j++) {
            float f0, f1;
            unpack2(acc2[j], f0, f1);
            int o0 = oBase + 2 * j;
            out[(size_t)(b * O_ + o0) * T + t]     = f0 + __ldg(bias + o0);
            out[(size_t)(b * O_ + o0 + 1) * T + t] = f1 + __ldg(bias + o0 + 1);
        }
    }
}

extern "C" void kernel_launch(void* const* d_in, const int* in_sizes, int n_in,
                              void* d_out, int out_size) {
    (void)in_sizes; (void)n_in;
    const float* x    = (const float*)d_in[0];
    const float* wt   = (const float*)d_in[1];
    const float* bias = (const float*)d_in[2];
    const int*   src  = (const int*)d_in[3];
    float* out = (float*)d_out;

    int T = out_size / (B_ * O_);   // 32768
    cudaFuncSetAttribute(astrf_kernel, cudaFuncAttributeMaxDynamicSharedMemorySize, SMEM_BYTES);
    dim3 grid(T / TT, O_ / OH, B_);
    astrf_kernel<<<grid, 512, SMEM_BYTES>>>(x, wt, bias, src, out, T);
}

// round 5
// speedup vs baseline: 1.4181x; 1.1842x over previous
#include <cuda_runtime.h>
#include <cuda_fp16.h>

// Problem constants
#define B_   4
#define IC   16      // inDim
#define S_   4096    // nSeq
#define O_   64      // outDim
#define W_   64      // nWin
#define OH   16      // outputs per CTA
#define TT   256     // time-tile per CTA
#define ECH  8       // events per chunk (2 groups of 4)

// Shared memory layout
//  wsm : fp16, [row=i*16+wq][o ^ (row&15)][4 halves] -> 256 rows x 128B = 32KB
//  trf : fp32, [e*64+w][20] (o padded 16->20)        -> 512*20*4 = 40KB
//  xs  : fp32, 2 buffers x [i*8 + e] = 2*128 floats
//  src : 2 buffers x 8 ints
#define TRF_OFF_F  8192                       // float index of trf
#define TRF_FLOATS 10240
#define XS_OFF_F   (TRF_OFF_F + TRF_FLOATS)   // 18432
#define SRC_OFF_F  (XS_OFF_F + 256)           // 18688
#define SMEM_FLOATS (SRC_OFF_F + 16)
#define SMEM_BYTES  (SMEM_FLOATS * 4)         // ~74.8 KB

__device__ __forceinline__ unsigned long long ffma2(unsigned long long a,
                                                    unsigned long long b,
                                                    unsigned long long c) {
    unsigned long long d;
    asm("fma.rn.f32x2 %0, %1, %2, %3;" : "=l"(d) : "l"(a), "l"(b), "l"(c));
    return d;
}
__device__ __forceinline__ unsigned long long add2(unsigned long long a,
                                                   unsigned long long b) {
    unsigned long long d;
    asm("add.rn.f32x2 %0, %1, %2;" : "=l"(d) : "l"(a), "l"(b));
    return d;
}
__device__ __forceinline__ unsigned long long pack2(float lo, float hi) {
    unsigned long long d;
    asm("mov.b64 %0, {%1, %2};" : "=l"(d) : "f"(lo), "f"(hi));
    return d;
}
__device__ __forceinline__ void unpack2(unsigned long long v, float& lo, float& hi) {
    asm("mov.b64 {%0, %1}, %2;" : "=f"(lo), "=f"(hi) : "l"(v));
}

__global__ __launch_bounds__(512, 2)
void astrf_kernel(const float* __restrict__ x, const float* __restrict__ wt,
                  const float* __restrict__ bias, const int* __restrict__ srcIdx,
                  float* __restrict__ out, int T)
{
    extern __shared__ float smem[];
    __half* wsm  = (__half*)smem;               // 16384 halves
    float* trf   = smem + TRF_OFF_F;
    float* xs    = smem + XS_OFF_F;
    int*   srcsm = (int*)(smem + SRC_OFF_F);

    const int tid   = threadIdx.x;
    const int b     = blockIdx.z;
    const int oBase = blockIdx.y * OH;
    const int t0    = blockIdx.x * TT;

    // ---- Stage weights: gmem f32 -> smem f16, XOR-swizzled conflict-free.
    // 16 warps, one output channel per warp; each warp covers ALL 256 rows.
    {
        const int o    = tid >> 5;          // warp id = output channel (0..15)
        const int lane = tid & 31;
        const float4* gw = (const float4*)(wt + (size_t)(oBase + o) * (IC * W_));
        uint2* wsm2 = (uint2*)wsm;          // [row][16] of half4
        #pragma unroll
        for (int u = 0; u < 8; u++) {
            int row = lane + u * 32;                   // 0..255 = i*16 + wq
            float4 v = gw[row];
            __half2 h01 = __floats2half2_rn(v.x, v.y);
            __half2 h23 = __floats2half2_rn(v.z, v.w);
            uint2 hv;
            hv.x = *(unsigned*)&h01; hv.y = *(unsigned*)&h23;
            wsm2[row * 16 + (o ^ (row & 15))] = hv;
        }
    }

    // ---- Per-thread binary search for event window [t0-(W-1), t0+TT)
    int sLo, sHi;
    {
        const int* sp = srcIdx + b * S_;
        int lo = 0, hi = S_, tgt = t0 - (W_ - 1);
        while (lo < hi) { int m = (lo + hi) >> 1; if (sp[m] < tgt) lo = m + 1; else hi = m; }
        sLo = lo;
        lo = 0; hi = S_; tgt = t0 + TT;
        while (lo < hi) { int m = (lo + hi) >> 1; if (sp[m] < tgt) lo = m + 1; else hi = m; }
        sHi = lo;
    }

    // Thread roles
    const int oA  = tid & 15;            // Phase A: output lane
    const int wqA = (tid >> 4) & 15;     // Phase A: w-quad
    const int egA = tid >> 8;            // event group (0/1)
    const int tlB = tid & 255;           // Phase B: time offset within tile

    // Phase-A weight pointer (swizzle term == wqA, constant per thread)
    const uint2* wA = (const uint2*)wsm + wqA * 16 + (oA ^ wqA);

    // Persistent accumulators: 16 outputs as 8 f32x2
    unsigned long long acc2[8];
    #pragma unroll
    for (int k = 0; k < 8; k++) acc2[k] = 0ull;

    // ---- x/src staging (x stored plain, duplicated in registers later)
    auto stage = [&](int c0, int buf) {
        if (tid < 128) {
            int i = tid >> 3, e = tid & 7;
            float v = (c0 + e < sHi) ? x[(size_t)(b * IC + i) * S_ + c0 + e] : 0.f;
            xs[buf * 128 + i * 8 + e] = v;
        } else if (tid < 136) {
            int k = tid - 128;
            srcsm[buf * 8 + k] = (c0 + k < sHi) ? srcIdx[b * S_ + c0 + k] : (1 << 29);
        }
    };
    stage(sLo, 0);
    __syncthreads();

    int cur = 0;
    for (int c0 = sLo; c0 < sHi; c0 += ECH) {
        // ---- Phase A: trf[e][w][o] = sum_i x[i,e] * w[o,i,w]
        unsigned long long a2[4][2];
        #pragma unroll
        for (int le = 0; le < 4; le++) { a2[le][0] = 0ull; a2[le][1] = 0ull; }

        const float* xb = xs + cur * 128 + egA * 4;
        #pragma unroll
        for (int i = 0; i < IC; i++) {
            uint2 hv = wA[i * 256];                        // conflict-free LDS.64
            float2 f01 = __half22float2(*(__half2*)&hv.x);
            float2 f23 = __half22float2(*(__half2*)&hv.y);
            unsigned long long w01 = pack2(f01.x, f01.y);
            unsigned long long w23 = pack2(f23.x, f23.y);
            float4 xv = *(const float4*)(xb + i * 8);      // broadcast LDS.128
            unsigned long long x0 = pack2(xv.x, xv.x);
            unsigned long long x1 = pack2(xv.y, xv.y);
            unsigned long long x2 = pack2(xv.z, xv.z);
            unsigned long long x3 = pack2(xv.w, xv.w);
            a2[0][0] = ffma2(w01, x0, a2[0][0]);
            a2[0][1] = ffma2(w23, x0, a2[0][1]);
            a2[1][0] = ffma2(w01, x1, a2[1][0]);
            a2[1][1] = ffma2(w23, x1, a2[1][1]);
            a2[2][0] = ffma2(w01, x2, a2[2][0]);
            a2[2][1] = ffma2(w23, x2, a2[2][1]);
            a2[3][0] = ffma2(w01, x3, a2[3][0]);
            a2[3][1] = ffma2(w23, x3, a2[3][1]);
        }
        // store trf rows (e*64 + wq*4 + k) at offset o : conflict-free halves
        #pragma unroll
        for (int le = 0; le < 4; le++) {
            int e = egA * 4 + le;
            float f0, f1, f2, f3;
            unpack2(a2[le][0], f0, f1);
            unpack2(a2[le][1], f2, f3);
            float* p = trf + (e * 64 + wqA * 4) * 20 + oA;
            p[0] = f0; p[20] = f1; p[40] = f2; p[60] = f3;
        }
        __syncthreads();   // trf ready; xs[cur] fully consumed

        // ---- Stage next chunk into the other buffer (overlaps Phase B)
        if (c0 + ECH < sHi) stage(c0 + ECH, cur ^ 1);

        // ---- Phase B: overlap-add, 4 LDS.128 per event hit, no atomics
        {
            const int t = t0 + tlB;
            const int* sp = srcsm + cur * 8 + egA * 4;
            #pragma unroll
            for (int le = 0; le < 4; le++) {
                int w = t - sp[le];
                if ((unsigned)w < (unsigned)W_) {
                    int e = egA * 4 + le;
                    const ulonglong2* p =
                        (const ulonglong2*)(trf + (e * 64 + w) * 20);
                    #pragma unroll
                    for (int j = 0; j < 4; j++) {
                        ulonglong2 v = p[j];
                        acc2[2*j]   = add2(acc2[2*j],   v.x);
                        acc2[2*j+1] = add2(acc2[2*j+1], v.y);
                    }
                }
            }
        }
        __syncthreads();   // Phase B done reading trf; next x staged
        cur ^= 1;
    }

    // ---- Epilogue: combine event-group partials via trf buffer, bias, store
    if (egA == 1) {
        ulonglong2* bp = (ulonglong2*)trf + tlB * 4;
        #pragma unroll
        for (int j = 0; j < 4; j++) {
            ulonglong2 v; v.x = acc2[2*j]; v.y = acc2[2*j+1];
            bp[j] = v;
        }
    }
    __syncthreads();
    if (egA == 0) {
        const ulonglong2* bp = (const ulonglong2*)trf + tlB * 4;
        #pragma unroll
        for (int j = 0; j < 4; j++) {
            ulonglong2 v = bp[j];
            acc2[2*j]   = add2(acc2[2*j],   v.x);
            acc2[2*j+1] = add2(acc2[2*j+1], v.y);
        }
        const int t = t0 + tlB;
        #pragma unroll
        for (int j = 0; j < 8; j++) {
            float f0, f1;
            unpack2(acc2[j], f0, f1);
            int o0 = oBase + 2 * j;
            out[(size_t)(b * O_ + o0) * T + t]     = f0 + __ldg(bias + o0);
            out[(size_t)(b * O_ + o0 + 1) * T + t] = f1 + __ldg(bias + o0 + 1);
        }
    }
}

extern "C" void kernel_launch(void* const* d_in, const int* in_sizes, int n_in,
                              void* d_out, int out_size) {
    (void)in_sizes; (void)n_in;
    const float* x    = (const float*)d_in[0];
    const float* wt   = (const float*)d_in[1];
    const float* bias = (const float*)d_in[2];
    const int*   src  = (const int*)d_in[3];
    float* out = (float*)d_out;

    int T = out_size / (B_ * O_);   // 32768
    cudaFuncSetAttribute(astrf_kernel, cudaFuncAttributeMaxDynamicSharedMemorySize, SMEM_BYTES);
    dim3 grid(T / TT, O_ / OH, B_);
    astrf_kernel<<<grid, 512, SMEM_BYTES>>>(x, wt, bias, src, out, T);
}

// round 6
// speedup vs baseline: 1.7568x; 1.2389x over previous
#include <cuda_runtime.h>
#include <cuda_fp16.h>

// Problem constants
#define B_   4
#define IC   16      // inDim
#define S_   4096    // nSeq
#define O_   64      // outDim
#define W_   64      // nWin
#define OH   16      // outputs per CTA
#define TT   256     // time-tile per CTA
#define ECH  8       // events per chunk (all handled by every thread)

// Shared memory layout (float indices)
//  wsm : fp16, [row=i*16+wq][o ^ (row&15)][4 halves] -> 256 rows x 128B = 32KB
//  trf : fp32, [e*64+w][20] (o padded 16->20)        -> 512*20*4 = 40KB
//  xs  : fp32, 2 buffers x [i*8 + e] = 2*128 floats
//  src : 2 buffers x 8 ints
#define TRF_OFF_F  8192
#define TRF_FLOATS 10240
#define XS_OFF_F   (TRF_OFF_F + TRF_FLOATS)   // 18432
#define SRC_OFF_F  (XS_OFF_F + 256)           // 18688
#define SMEM_FLOATS (SRC_OFF_F + 16)
#define SMEM_BYTES  (SMEM_FLOATS * 4)         // 74816 B -> 3 CTAs/SM

__device__ __forceinline__ unsigned long long ffma2(unsigned long long a,
                                                    unsigned long long b,
                                                    unsigned long long c) {
    unsigned long long d;
    asm("fma.rn.f32x2 %0, %1, %2, %3;" : "=l"(d) : "l"(a), "l"(b), "l"(c));
    return d;
}
__device__ __forceinline__ unsigned long long add2(unsigned long long a,
                                                   unsigned long long b) {
    unsigned long long d;
    asm("add.rn.f32x2 %0, %1, %2;" : "=l"(d) : "l"(a), "l"(b));
    return d;
}
__device__ __forceinline__ unsigned long long pack2(float lo, float hi) {
    unsigned long long d;
    asm("mov.b64 %0, {%1, %2};" : "=l"(d) : "f"(lo), "f"(hi));
    return d;
}
__device__ __forceinline__ void unpack2(unsigned long long v, float& lo, float& hi) {
    asm("mov.b64 {%0, %1}, %2;" : "=f"(lo), "=f"(hi) : "l"(v));
}

__global__ __launch_bounds__(256, 3)
void astrf_kernel(const float* __restrict__ x, const float* __restrict__ wt,
                  const float* __restrict__ bias, const int* __restrict__ srcIdx,
                  float* __restrict__ out, int T)
{
    extern __shared__ float smem[];
    __half* wsm  = (__half*)smem;               // 16384 halves
    float* trf   = smem + TRF_OFF_F;
    float* xs    = smem + XS_OFF_F;
    int*   srcsm = (int*)(smem + SRC_OFF_F);

    const int tid   = threadIdx.x;
    const int b     = blockIdx.z;
    const int oBase = blockIdx.y * OH;
    const int t0    = blockIdx.x * TT;

    // ---- Stage weights: gmem f32 -> smem f16, XOR-swizzled conflict-free.
    // 8 warps; each warp stages two output channels (o and o+8), all 256 rows.
    {
        const int lane = tid & 31;
        uint2* wsm2 = (uint2*)wsm;          // [row][16] of half4
        #pragma unroll
        for (int r = 0; r < 2; r++) {
            const int o = (tid >> 5) + r * 8;     // 0..15
            const float4* gw = (const float4*)(wt + (size_t)(oBase + o) * (IC * W_));
            #pragma unroll
            for (int u = 0; u < 8; u++) {
                int row = lane + u * 32;                   // 0..255 = i*16 + wq
                float4 v = gw[row];
                __half2 h01 = __floats2half2_rn(v.x, v.y);
                __half2 h23 = __floats2half2_rn(v.z, v.w);
                uint2 hv;
                hv.x = *(unsigned*)&h01; hv.y = *(unsigned*)&h23;
                wsm2[row * 16 + (o ^ (row & 15))] = hv;
            }
        }
    }

    // ---- Per-thread binary search for event window [t0-(W-1), t0+TT)
    int sLo, sHi;
    {
        const int* sp = srcIdx + b * S_;
        int lo = 0, hi = S_, tgt = t0 - (W_ - 1);
        while (lo < hi) { int m = (lo + hi) >> 1; if (sp[m] < tgt) lo = m + 1; else hi = m; }
        sLo = lo;
        lo = 0; hi = S_; tgt = t0 + TT;
        while (lo < hi) { int m = (lo + hi) >> 1; if (sp[m] < tgt) lo = m + 1; else hi = m; }
        sHi = lo;
    }

    // Thread roles
    const int oA  = tid & 15;            // Phase A: output lane
    const int wqA = tid >> 4;            // Phase A: w-quad (0..15)

    // Phase-A weight pointer (swizzle term == wqA, constant per thread)
    const uint2* wA = (const uint2*)wsm + wqA * 16 + (oA ^ wqA);

    // Persistent accumulators: 16 outputs as 8 f32x2
    unsigned long long acc2[8];
    #pragma unroll
    for (int k = 0; k < 8; k++) acc2[k] = 0ull;

    // ---- x/src staging (x stored plain, duplicated in registers later)
    auto stage = [&](int c0, int buf) {
        if (tid < 128) {
            int i = tid >> 3, e = tid & 7;
            float v = (c0 + e < sHi) ? x[(size_t)(b * IC + i) * S_ + c0 + e] : 0.f;
            xs[buf * 128 + i * 8 + e] = v;
        } else if (tid < 136) {
            int k = tid - 128;
            srcsm[buf * 8 + k] = (c0 + k < sHi) ? srcIdx[b * S_ + c0 + k] : (1 << 29);
        }
    };
    stage(sLo, 0);
    __syncthreads();

    int cur = 0;
    for (int c0 = sLo; c0 < sHi; c0 += ECH) {
        // ---- Phase A: trf[e][w][o] = sum_i x[i,e] * w[o,i,w], all 8 events
        unsigned long long a2[ECH][2];
        #pragma unroll
        for (int e = 0; e < ECH; e++) { a2[e][0] = 0ull; a2[e][1] = 0ull; }

        const float* xb = xs + cur * 128;
        #pragma unroll
        for (int i = 0; i < IC; i++) {
            uint2 hv = wA[i * 256];                        // conflict-free LDS.64
            float2 f01 = __half22float2(*(__half2*)&hv.x);
            float2 f23 = __half22float2(*(__half2*)&hv.y);
            unsigned long long w01 = pack2(f01.x, f01.y);
            unsigned long long w23 = pack2(f23.x, f23.y);
            float4 xv0 = *(const float4*)(xb + i * 8);     // broadcast LDS.128
            float4 xv1 = *(const float4*)(xb + i * 8 + 4); // broadcast LDS.128
            unsigned long long xe[ECH];
            xe[0] = pack2(xv0.x, xv0.x);
            xe[1] = pack2(xv0.y, xv0.y);
            xe[2] = pack2(xv0.z, xv0.z);
            xe[3] = pack2(xv0.w, xv0.w);
            xe[4] = pack2(xv1.x, xv1.x);
            xe[5] = pack2(xv1.y, xv1.y);
            xe[6] = pack2(xv1.z, xv1.z);
            xe[7] = pack2(xv1.w, xv1.w);
            #pragma unroll
            for (int e = 0; e < ECH; e++) {
                a2[e][0] = ffma2(w01, xe[e], a2[e][0]);
                a2[e][1] = ffma2(w23, xe[e], a2[e][1]);
            }
        }
        // store trf rows (e*64 + wq*4 + k) at offset o : conflict-free
        #pragma unroll
        for (int e = 0; e < ECH; e++) {
            float f0, f1, f2, f3;
            unpack2(a2[e][0], f0, f1);
            unpack2(a2[e][1], f2, f3);
            float* p = trf + (e * 64 + wqA * 4) * 20 + oA;
            p[0] = f0; p[20] = f1; p[40] = f2; p[60] = f3;
        }
        __syncthreads();   // trf ready; xs[cur] fully consumed

        // ---- Stage next chunk into the other buffer (overlaps Phase B)
        if (c0 + ECH < sHi) stage(c0 + ECH, cur ^ 1);

        // ---- Phase B: overlap-add, 4 LDS.128 per event hit, no atomics
        {
            const int t = t0 + tid;
            const int* sp = srcsm + cur * 8;
            #pragma unroll
            for (int e = 0; e < ECH; e++) {
                int w = t - sp[e];
                if ((unsigned)w < (unsigned)W_) {
                    const ulonglong2* p =
                        (const ulonglong2*)(trf + (e * 64 + w) * 20);
                    #pragma unroll
                    for (int j = 0; j < 4; j++) {
                        ulonglong2 v = p[j];
                        acc2[2*j]   = add2(acc2[2*j],   v.x);
                        acc2[2*j+1] = add2(acc2[2*j+1], v.y);
                    }
                }
            }
        }
        __syncthreads();   // Phase B done reading trf; next x staged
        cur ^= 1;
    }

    // ---- Epilogue: bias + direct coalesced store (lanes = consecutive t)
    {
        const int t = t0 + tid;
        #pragma unroll
        for (int j = 0; j < 8; j++) {
            float f0, f1;
            unpack2(acc2[j], f0, f1);
            int o0 = oBase + 2 * j;
            out[(size_t)(b * O_ + o0) * T + t]     = f0 + __ldg(bias + o0);
            out[(size_t)(b * O_ + o0 + 1) * T + t] = f1 + __ldg(bias + o0 + 1);
        }
    }
}

extern "C" void kernel_launch(void* const* d_in, const int* in_sizes, int n_in,
                              void* d_out, int out_size) {
    (void)in_sizes; (void)n_in;
    const float* x    = (const float*)d_in[0];
    const float* wt   = (const float*)d_in[1];
    const float* bias = (const float*)d_in[2];
    const int*   src  = (const int*)d_in[3];
    float* out = (float*)d_out;

    int T = out_size / (B_ * O_);   // 32768
    cudaFuncSetAttribute(astrf_kernel, cudaFuncAttributeMaxDynamicSharedMemorySize, SMEM_BYTES);
    dim3 grid(T / TT, O_ / OH, B_);
    astrf_kernel<<<grid, 256, SMEM_BYTES>>>(x, wt, bias, src, out, T);
}